// round 2
// baseline (speedup 1.0000x reference)
#include <cuda_runtime.h>
#include <math.h>

#define Hh 384
#define Ww 384
#define NC 10
#define HW (384*384)
#define BATCH 8
#define D64 64

// ---- scratch (static device globals: allocation-free) ----
__device__ float g_h[(size_t)BATCH * D64 * HW];   // 302 MB intermediate h
__device__ float g_stats[128];                    // [b][g][{sum,sumsq}]
__device__ float g_mean[64];
__device__ float g_rstd[64];

// ---------------- K0: zero stats ----------------
__global__ void k_zero() { g_stats[threadIdx.x] = 0.f; }

// ---------------- K1: softmax + neighbor features + W1 + stat partials ----
#define TLX 32
#define TLY 8
#define EX 36
#define EY 12

__global__ __launch_bounds__(256) void k_feat(const float* __restrict__ x,
                                              const float* __restrict__ W1,
                                              const float* __restrict__ b1) {
    __shared__ float P[NC * EY * EX];          // softmax probs, tile + 2px halo
    __shared__ __align__(16) float w1s[512];
    __shared__ float b1s[64];
    __shared__ float sstat[16];

    const int b  = blockIdx.z;
    const int r0 = blockIdx.y * TLY, c0 = blockIdx.x * TLX;
    const int tid = threadIdx.x;

    for (int i = tid; i < 512; i += 256) w1s[i] = W1[i];   // FIX: full 512-elem load
    if (tid < 64)  b1s[tid] = b1[tid];
    if (tid < 16)  sstat[tid] = 0.f;

    // softmax over C for extended (halo) tile, replicate padding via clamp
    const float* xb = x + (size_t)b * NC * HW;
    for (int i = tid; i < EX * EY; i += 256) {
        int er = i / EX, ec = i % EX;
        int gr = min(max(r0 + er - 2, 0), Hh - 1);
        int gc = min(max(c0 + ec - 2, 0), Ww - 1);
        const float* xp = xb + gr * Ww + gc;
        float v[NC];
        float m = -1e30f;
#pragma unroll
        for (int c = 0; c < NC; c++) { v[c] = xp[(size_t)c * HW]; m = fmaxf(m, v[c]); }
        float s = 0.f;
#pragma unroll
        for (int c = 0; c < NC; c++) { v[c] = __expf(v[c] - m); s += v[c]; }
        float inv = 1.f / s;
#pragma unroll
        for (int c = 0; c < NC; c++) P[c * EY * EX + i] = v[c] * inv;
    }
    __syncthreads();

    const int tx = tid & 31, ty = tid >> 5;
    float match3 = 0.f, ent3 = 0.f, var3 = 0.f, maj3 = 0.f;
    float match5 = 0.f, ent5 = 0.f, var5 = 0.f, maj5 = 0.f;

#pragma unroll 1
    for (int c = 0; c < NC; c++) {
        const float* Pc = &P[c * EY * EX + ty * EX + tx];
        float s3 = 0.f, q3 = 0.f, s5 = 0.f, q5 = 0.f;
#pragma unroll
        for (int dr = 0; dr < 5; dr++) {
#pragma unroll
            for (int dc = 0; dc < 5; dc++) {
                float p = Pc[dr * EX + dc];
                s5 += p; q5 += p * p;
                if (dr >= 1 && dr <= 3 && dc >= 1 && dc <= 3) { s3 += p; q3 += p * p; }
            }
        }
        float pcen = Pc[2 * EX + 2];
        match3 += pcen * (s3 - pcen);
        match5 += pcen * (s5 - pcen);
        maj3 = fmaxf(maj3, s3);
        maj5 = fmaxf(maj5, s5);
        float pb3 = s3 * (1.f / 9.f),  pb5 = s5 * (1.f / 25.f);
        float pc3 = fmaxf(pb3, 1e-8f), pc5 = fmaxf(pb5, 1e-8f);
        ent3 -= pc3 * __logf(pc3);
        ent5 -= pc5 * __logf(pc5);
        var3 += q3 * (1.f / 9.f)  - pb3 * pb3;
        var5 += q5 * (1.f / 25.f) - pb5 * pb5;
    }

    const float INV_LOGC = 0.434294481903252f; // 1/ln(10)
    float f[8];
    f[0] = match3 * (1.f / 8.f);
    f[1] = maj3 * (1.f / 9.f);
    f[2] = 1.f - ent3 * INV_LOGC;
    f[3] = var3;
    f[4] = match5 * (1.f / 24.f);
    f[5] = maj5 * (1.f / 25.f);
    f[6] = 1.f - ent5 * INV_LOGC;
    f[7] = var5;

    // h = W1 f + b1 ; write to scratch ; accumulate per-group stats
    const int pix = (r0 + ty) * Ww + (c0 + tx);
    float* hb = g_h + (size_t)b * D64 * HW + pix;
    float gsum[8], gsq[8];
#pragma unroll
    for (int g = 0; g < 8; g++) { gsum[g] = 0.f; gsq[g] = 0.f; }
#pragma unroll
    for (int d = 0; d < 64; d++) {
        const float4 wa = *(const float4*)&w1s[d * 8];
        const float4 wb = *(const float4*)&w1s[d * 8 + 4];
        float acc = b1s[d];
        acc += wa.x * f[0] + wa.y * f[1] + wa.z * f[2] + wa.w * f[3];
        acc += wb.x * f[4] + wb.y * f[5] + wb.z * f[6] + wb.w * f[7];
        hb[(size_t)d * HW] = acc;
        gsum[d >> 3] += acc;
        gsq[d >> 3]  += acc * acc;
    }
    // warp reduce -> smem -> global atomics
#pragma unroll
    for (int g = 0; g < 8; g++) {
        float a = gsum[g], q = gsq[g];
#pragma unroll
        for (int o = 16; o; o >>= 1) {
            a += __shfl_xor_sync(0xffffffffu, a, o);
            q += __shfl_xor_sync(0xffffffffu, q, o);
        }
        if ((tid & 31) == 0) { atomicAdd(&sstat[2 * g], a); atomicAdd(&sstat[2 * g + 1], q); }
    }
    __syncthreads();
    if (tid < 16) atomicAdd(&g_stats[b * 16 + tid], sstat[tid]);
}

// ---------------- K2: finalize GN stats ----------------
__global__ void k_stats() {
    int i = threadIdx.x;
    if (i < 64) {
        const float invN = 1.f / (8.f * (float)HW);
        float s  = g_stats[2 * i];
        float ss = g_stats[2 * i + 1];
        float mean = s * invN;
        float var  = ss * invN - mean * mean;
        g_mean[i] = mean;
        g_rstd[i] = rsqrtf(var + 1e-5f);
    }
}

// ---------------- K3: GN + GELU + W2 (f32x2 packed GEMM) ----------------
__device__ __forceinline__ unsigned long long pack2(float x, float y) {
    unsigned long long r;
    asm("mov.b64 %0, {%1, %2};" : "=l"(r) : "f"(x), "f"(y));
    return r;
}
__device__ __forceinline__ unsigned long long fma2(unsigned long long a,
                                                   unsigned long long b,
                                                   unsigned long long c) {
    unsigned long long d;
    asm("fma.rn.f32x2 %0, %1, %2, %3;" : "=l"(d) : "l"(a), "l"(b), "l"(c));
    return d;
}

#define SMEM3 (64 * 256 * 4 + 4096 * 8 + 208 * 4)

__global__ __launch_bounds__(256) void k_out(const float* __restrict__ gnw,
                                             const float* __restrict__ gnb,
                                             const float* __restrict__ W2,
                                             const float* __restrict__ b2,
                                             float* __restrict__ out) {
    extern __shared__ char sraw[];
    float* G = (float*)sraw;                                           // [64][256]
    unsigned long long* w2p = (unsigned long long*)(sraw + 64 * 256 * 4); // [d][d2] {w,w}
    float* sp = (float*)(sraw + 64 * 256 * 4 + 4096 * 8); // 0..7 mean, 8..15 rstd, 16 gnw, 80 gnb, 144 b2

    const int b  = blockIdx.y;
    const int p0 = blockIdx.x * 256;
    const int t  = threadIdx.x;

    if (t < 64) { sp[16 + t] = gnw[t]; sp[80 + t] = gnb[t]; sp[144 + t] = b2[t]; }
    if (t < 8)  { sp[t] = g_mean[b * 8 + t]; sp[8 + t] = g_rstd[b * 8 + t]; }
    for (int i = t; i < 4096; i += 256) {
        float w = W2[i];                       // W2[d2][d]
        w2p[(i & 63) * 64 + (i >> 6)] = pack2(w, w);   // transposed [d][d2]
    }
    __syncthreads();

    // GN + GELU into smem tile
    const float* hb = g_h + (size_t)b * D64 * HW + p0;
#pragma unroll 8
    for (int d = 0; d < 64; d++) {
        float hv = hb[(size_t)d * HW + t];
        int g = d >> 3;
        float hn = (hv - sp[g]) * sp[8 + g] * sp[16 + d] + sp[80 + d];
        float ge = 0.5f * hn * (1.f + erff(hn * 0.70710678118f));
        G[d * 256 + t] = ge;
    }
    __syncthreads();

    // out[64][256] = W2 @ G  (8 d2 x 4 pixel-pairs per thread, packed f32x2)
    const int d2b = (t >> 5) * 8;
    const int pxb = (t & 31) * 2;
    unsigned long long acc[8][4];
#pragma unroll
    for (int i = 0; i < 8; i++) {
        unsigned long long bv = pack2(sp[144 + d2b + i], sp[144 + d2b + i]);
#pragma unroll
        for (int j = 0; j < 4; j++) acc[i][j] = bv;
    }
#pragma unroll 4
    for (int d = 0; d < 64; d++) {
        unsigned long long g0 = *(const unsigned long long*)&G[d * 256 + pxb];
        unsigned long long g1 = *(const unsigned long long*)&G[d * 256 + pxb + 64];
        unsigned long long g2 = *(const unsigned long long*)&G[d * 256 + pxb + 128];
        unsigned long long g3 = *(const unsigned long long*)&G[d * 256 + pxb + 192];
        const unsigned long long* wrow = &w2p[d * 64 + d2b];
#pragma unroll
        for (int i = 0; i < 8; i++) {
            unsigned long long w = wrow[i];
            acc[i][0] = fma2(w, g0, acc[i][0]);
            acc[i][1] = fma2(w, g1, acc[i][1]);
            acc[i][2] = fma2(w, g2, acc[i][2]);
            acc[i][3] = fma2(w, g3, acc[i][3]);
        }
    }
    float* ob = out + (size_t)b * D64 * HW + p0;
#pragma unroll
    for (int i = 0; i < 8; i++) {
        size_t base = (size_t)(d2b + i) * HW;
        *(unsigned long long*)&ob[base + pxb]       = acc[i][0];
        *(unsigned long long*)&ob[base + pxb + 64]  = acc[i][1];
        *(unsigned long long*)&ob[base + pxb + 128] = acc[i][2];
        *(unsigned long long*)&ob[base + pxb + 192] = acc[i][3];
    }
}

// ---------------- launch ----------------
extern "C" void kernel_launch(void* const* d_in, const int* in_sizes, int n_in,
                              void* d_out, int out_size) {
    const float* x   = (const float*)d_in[0];
    const float* W1  = (const float*)d_in[1];
    const float* b1  = (const float*)d_in[2];
    const float* gnw = (const float*)d_in[3];
    const float* gnb = (const float*)d_in[4];
    const float* W2  = (const float*)d_in[5];
    const float* b2  = (const float*)d_in[6];
    float* out = (float*)d_out;

    k_zero<<<1, 128>>>();

    dim3 g1(Ww / TLX, Hh / TLY, BATCH);   // 12 x 48 x 8
    k_feat<<<g1, 256>>>(x, W1, b1);

    k_stats<<<1, 64>>>();

    cudaFuncSetAttribute(k_out, cudaFuncAttributeMaxDynamicSharedMemorySize, SMEM3);
    dim3 g3(HW / 256, BATCH);             // 576 x 8
    k_out<<<g3, 256, SMEM3>>>(gnw, gnb, W2, b2, out);
}

// round 3
// speedup vs baseline: 1.2214x; 1.2214x over previous
#include <cuda_runtime.h>
#include <math.h>

#define Hh 384
#define Ww 384
#define NC 10
#define HW (384*384)
#define BATCH 8
#define D64 64

typedef unsigned long long u64;

// ---- scratch (static device globals: allocation-free) ----
__device__ float g_h[(size_t)BATCH * D64 * HW];   // 302 MB intermediate h
__device__ float g_stats[128];                    // [b][g][{sum,sumsq}]
__device__ float g_mean[64];
__device__ float g_rstd[64];

// ---------------- K0: zero stats ----------------
__global__ void k_zero() { g_stats[threadIdx.x] = 0.f; }

// ---------------- K1: softmax + neighbor features + W1 + stat partials ----
#define TLX 32
#define TLY 8
#define EX 36
#define EY 12

__global__ __launch_bounds__(256) void k_feat(const float* __restrict__ x,
                                              const float* __restrict__ W1,
                                              const float* __restrict__ b1) {
    __shared__ float P[NC * EY * EX];          // softmax probs, tile + 2px halo
    __shared__ __align__(16) float w1s[512];
    __shared__ float b1s[64];
    __shared__ float sstat[16];

    const int b  = blockIdx.z;
    const int r0 = blockIdx.y * TLY, c0 = blockIdx.x * TLX;
    const int tid = threadIdx.x;

    for (int i = tid; i < 512; i += 256) w1s[i] = W1[i];
    if (tid < 64)  b1s[tid] = b1[tid];
    if (tid < 16)  sstat[tid] = 0.f;

    // softmax over C for extended (halo) tile, replicate padding via clamp
    const float* xb = x + (size_t)b * NC * HW;
    for (int i = tid; i < EX * EY; i += 256) {
        int er = i / EX, ec = i % EX;
        int gr = min(max(r0 + er - 2, 0), Hh - 1);
        int gc = min(max(c0 + ec - 2, 0), Ww - 1);
        const float* xp = xb + gr * Ww + gc;
        float v[NC];
        float m = -1e30f;
#pragma unroll
        for (int c = 0; c < NC; c++) { v[c] = xp[(size_t)c * HW]; m = fmaxf(m, v[c]); }
        float s = 0.f;
#pragma unroll
        for (int c = 0; c < NC; c++) { v[c] = __expf(v[c] - m); s += v[c]; }
        float inv = 1.f / s;
#pragma unroll
        for (int c = 0; c < NC; c++) P[c * EY * EX + i] = v[c] * inv;
    }
    __syncthreads();

    const int tx = tid & 31, ty = tid >> 5;
    float match3 = 0.f, ent3 = 0.f, var3 = 0.f, maj3 = 0.f;
    float match5 = 0.f, ent5 = 0.f, var5 = 0.f, maj5 = 0.f;

#pragma unroll 1
    for (int c = 0; c < NC; c++) {
        const float* Pc = &P[c * EY * EX + ty * EX + tx];
        float s3 = 0.f, q3 = 0.f, s5 = 0.f, q5 = 0.f;
#pragma unroll
        for (int dr = 0; dr < 5; dr++) {
#pragma unroll
            for (int dc = 0; dc < 5; dc++) {
                float p = Pc[dr * EX + dc];
                s5 += p; q5 += p * p;
                if (dr >= 1 && dr <= 3 && dc >= 1 && dc <= 3) { s3 += p; q3 += p * p; }
            }
        }
        float pcen = Pc[2 * EX + 2];
        match3 += pcen * (s3 - pcen);
        match5 += pcen * (s5 - pcen);
        maj3 = fmaxf(maj3, s3);
        maj5 = fmaxf(maj5, s5);
        float pb3 = s3 * (1.f / 9.f),  pb5 = s5 * (1.f / 25.f);
        float pc3 = fmaxf(pb3, 1e-8f), pc5 = fmaxf(pb5, 1e-8f);
        ent3 -= pc3 * __logf(pc3);
        ent5 -= pc5 * __logf(pc5);
        var3 += q3 * (1.f / 9.f)  - pb3 * pb3;
        var5 += q5 * (1.f / 25.f) - pb5 * pb5;
    }

    const float INV_LOGC = 0.434294481903252f; // 1/ln(10)
    float f[8];
    f[0] = match3 * (1.f / 8.f);
    f[1] = maj3 * (1.f / 9.f);
    f[2] = 1.f - ent3 * INV_LOGC;
    f[3] = var3;
    f[4] = match5 * (1.f / 24.f);
    f[5] = maj5 * (1.f / 25.f);
    f[6] = 1.f - ent5 * INV_LOGC;
    f[7] = var5;

    // h = W1 f + b1 ; write to scratch ; accumulate per-group stats
    const int pix = (r0 + ty) * Ww + (c0 + tx);
    float* hb = g_h + (size_t)b * D64 * HW + pix;
    float gsum[8], gsq[8];
#pragma unroll
    for (int g = 0; g < 8; g++) { gsum[g] = 0.f; gsq[g] = 0.f; }
#pragma unroll
    for (int d = 0; d < 64; d++) {
        const float4 wa = *(const float4*)&w1s[d * 8];
        const float4 wb = *(const float4*)&w1s[d * 8 + 4];
        float acc = b1s[d];
        acc += wa.x * f[0] + wa.y * f[1] + wa.z * f[2] + wa.w * f[3];
        acc += wb.x * f[4] + wb.y * f[5] + wb.z * f[6] + wb.w * f[7];
        hb[(size_t)d * HW] = acc;
        gsum[d >> 3] += acc;
        gsq[d >> 3]  += acc * acc;
    }
    // warp reduce -> smem -> global atomics
#pragma unroll
    for (int g = 0; g < 8; g++) {
        float a = gsum[g], q = gsq[g];
#pragma unroll
        for (int o = 16; o; o >>= 1) {
            a += __shfl_xor_sync(0xffffffffu, a, o);
            q += __shfl_xor_sync(0xffffffffu, q, o);
        }
        if ((tid & 31) == 0) { atomicAdd(&sstat[2 * g], a); atomicAdd(&sstat[2 * g + 1], q); }
    }
    __syncthreads();
    if (tid < 16) atomicAdd(&g_stats[b * 16 + tid], sstat[tid]);
}

// ---------------- K2: finalize GN stats ----------------
__global__ void k_stats() {
    int i = threadIdx.x;
    if (i < 64) {
        const float invN = 1.f / (8.f * (float)HW);
        float s  = g_stats[2 * i];
        float ss = g_stats[2 * i + 1];
        float mean = s * invN;
        float var  = ss * invN - mean * mean;
        g_mean[i] = mean;
        g_rstd[i] = rsqrtf(var + 1e-5f);
    }
}

// ---------------- K3: GN + GELU + W2 (f32x2 packed GEMM, LDS.128) ----------
__device__ __forceinline__ u64 pack2(float x, float y) {
    u64 r;
    asm("mov.b64 %0, {%1, %2};" : "=l"(r) : "f"(x), "f"(y));
    return r;
}
__device__ __forceinline__ u64 fma2(u64 a, u64 b, u64 c) {
    u64 d;
    asm("fma.rn.f32x2 %0, %1, %2, %3;" : "=l"(d) : "l"(a), "l"(b), "l"(c));
    return d;
}

#define SMEM3 (64 * 256 * 4 + 4096 * 8 + 208 * 4)

__global__ __launch_bounds__(256, 2) void k_out(const float* __restrict__ gnw,
                                                const float* __restrict__ gnb,
                                                const float* __restrict__ W2,
                                                const float* __restrict__ b2,
                                                float* __restrict__ out) {
    extern __shared__ char sraw[];
    float* G = (float*)sraw;                               // [64][256]
    u64* w2p = (u64*)(sraw + 64 * 256 * 4);                // [d][d2] {w,w}
    float* sp = (float*)(sraw + 64 * 256 * 4 + 4096 * 8);  // mean/rstd/gnw/gnb/b2

    const int b  = blockIdx.y;
    const int p0 = blockIdx.x * 256;
    const int t  = threadIdx.x;

    if (t < 64) { sp[16 + t] = gnw[t]; sp[80 + t] = gnb[t]; sp[144 + t] = b2[t]; }
    if (t < 8)  { sp[t] = g_mean[b * 8 + t]; sp[8 + t] = g_rstd[b * 8 + t]; }
    for (int i = t; i < 4096; i += 256) {
        float w = W2[i];                              // W2[d2][d]
        w2p[(i & 63) * 64 + (i >> 6)] = pack2(w, w);  // transposed [d][d2]
    }
    __syncthreads();

    // ---- GN + GELU into smem tile, vectorized (4 px per thread per step) ----
    {
        const float* hb = g_h + (size_t)b * D64 * HW + p0;
        const int dq = t >> 6;          // 0..3
        const int px = (t & 63) * 4;    // 0..252
#pragma unroll
        for (int it = 0; it < 16; it++) {
            int d = it * 4 + dq;
            int g = d >> 3;
            float a = sp[8 + g] * sp[16 + d];
            float c = sp[80 + d] - sp[g] * a;
            float4 hv = *(const float4*)&hb[(size_t)d * HW + px];
            float4 r;
            float h0 = fmaf(hv.x, a, c);
            float h1 = fmaf(hv.y, a, c);
            float h2 = fmaf(hv.z, a, c);
            float h3 = fmaf(hv.w, a, c);
            r.x = 0.5f * h0 * (1.f + erff(h0 * 0.70710678118f));
            r.y = 0.5f * h1 * (1.f + erff(h1 * 0.70710678118f));
            r.z = 0.5f * h2 * (1.f + erff(h2 * 0.70710678118f));
            r.w = 0.5f * h3 * (1.f + erff(h3 * 0.70710678118f));
            *(float4*)&G[d * 256 + px] = r;
        }
    }
    __syncthreads();

    // ---- out[64][256] = W2 @ G : 8 d2 x 8 px (4 pairs) per thread ----
    const int d2b = (t >> 5) * 8;
    const int p4  = (t & 31) * 4;      // pixels p4..p4+3 and p4+128..p4+131
    u64 acc[8][4];
#pragma unroll
    for (int i = 0; i < 8; i++) {
        float bv = sp[144 + d2b + i];
        u64 bp = pack2(bv, bv);
#pragma unroll
        for (int j = 0; j < 4; j++) acc[i][j] = bp;
    }

#pragma unroll 4
    for (int d = 0; d < 64; d++) {
        ulonglong2 ga = *(const ulonglong2*)&G[d * 256 + p4];         // pairs (p4,p4+1),(p4+2,p4+3)
        ulonglong2 gb = *(const ulonglong2*)&G[d * 256 + p4 + 128];   // pairs (+128..)
        const ulonglong2* wr = (const ulonglong2*)&w2p[d * 64 + d2b]; // warp-uniform
        u64 wv[8];
        *(ulonglong2*)&wv[0] = wr[0];
        *(ulonglong2*)&wv[2] = wr[1];
        *(ulonglong2*)&wv[4] = wr[2];
        *(ulonglong2*)&wv[6] = wr[3];
#pragma unroll
        for (int i = 0; i < 8; i++) {
            acc[i][0] = fma2(wv[i], ga.x, acc[i][0]);
            acc[i][1] = fma2(wv[i], ga.y, acc[i][1]);
            acc[i][2] = fma2(wv[i], gb.x, acc[i][2]);
            acc[i][3] = fma2(wv[i], gb.y, acc[i][3]);
        }
    }

    float* ob = out + (size_t)b * D64 * HW + p0;
#pragma unroll
    for (int i = 0; i < 8; i++) {
        size_t base = (size_t)(d2b + i) * HW;
        ulonglong2 s0; s0.x = acc[i][0]; s0.y = acc[i][1];
        ulonglong2 s1; s1.x = acc[i][2]; s1.y = acc[i][3];
        *(ulonglong2*)&ob[base + p4]       = s0;
        *(ulonglong2*)&ob[base + p4 + 128] = s1;
    }
}

// ---------------- launch ----------------
extern "C" void kernel_launch(void* const* d_in, const int* in_sizes, int n_in,
                              void* d_out, int out_size) {
    const float* x   = (const float*)d_in[0];
    const float* W1  = (const float*)d_in[1];
    const float* b1  = (const float*)d_in[2];
    const float* gnw = (const float*)d_in[3];
    const float* gnb = (const float*)d_in[4];
    const float* W2  = (const float*)d_in[5];
    const float* b2  = (const float*)d_in[6];
    float* out = (float*)d_out;

    k_zero<<<1, 128>>>();

    dim3 g1(Ww / TLX, Hh / TLY, BATCH);   // 12 x 48 x 8
    k_feat<<<g1, 256>>>(x, W1, b1);

    k_stats<<<1, 64>>>();

    cudaFuncSetAttribute(k_out, cudaFuncAttributeMaxDynamicSharedMemorySize, SMEM3);
    dim3 g3(HW / 256, BATCH);             // 576 x 8
    k_out<<<g3, 256, SMEM3>>>(gnw, gnb, W2, b2, out);
}

// round 4
// speedup vs baseline: 1.2489x; 1.0225x over previous
#include <cuda_runtime.h>
#include <math.h>

#define Hh 384
#define Ww 384
#define NC 10
#define HW (384*384)
#define BATCH 8
#define D64 64

typedef unsigned long long u64;

// ---- scratch (static device globals: allocation-free) ----
__device__ float g_h[(size_t)BATCH * D64 * HW];   // 302 MB intermediate h
__device__ float g_stats[128];                    // [b][g][{sum,sumsq}]
__device__ float g_mean[64];
__device__ float g_rstd[64];

// ---------------- K0: zero stats ----------------
__global__ void k_zero() { g_stats[threadIdx.x] = 0.f; }

// ---------------- K1: softmax + neighbor features + W1 + stat partials ----
#define TLX 32
#define TLY 8
#define EX 36
#define EY 12

__global__ __launch_bounds__(256) void k_feat(const float* __restrict__ x,
                                              const float* __restrict__ W1,
                                              const float* __restrict__ b1) {
    __shared__ float P[NC * EY * EX];          // softmax probs, tile + 2px halo
    __shared__ __align__(16) float w1s[512];
    __shared__ float b1s[64];
    __shared__ float sstat[16];

    const int b  = blockIdx.z;
    const int r0 = blockIdx.y * TLY, c0 = blockIdx.x * TLX;
    const int tid = threadIdx.x;

    for (int i = tid; i < 512; i += 256) w1s[i] = W1[i];
    if (tid < 64)  b1s[tid] = b1[tid];
    if (tid < 16)  sstat[tid] = 0.f;

    // softmax over C for extended (halo) tile, replicate padding via clamp
    const float* xb = x + (size_t)b * NC * HW;
    for (int i = tid; i < EX * EY; i += 256) {
        int er = i / EX, ec = i % EX;
        int gr = min(max(r0 + er - 2, 0), Hh - 1);
        int gc = min(max(c0 + ec - 2, 0), Ww - 1);
        const float* xp = xb + gr * Ww + gc;
        float v[NC];
        float m = -1e30f;
#pragma unroll
        for (int c = 0; c < NC; c++) { v[c] = xp[(size_t)c * HW]; m = fmaxf(m, v[c]); }
        float s = 0.f;
#pragma unroll
        for (int c = 0; c < NC; c++) { v[c] = __expf(v[c] - m); s += v[c]; }
        float inv = 1.f / s;
#pragma unroll
        for (int c = 0; c < NC; c++) P[c * EY * EX + i] = v[c] * inv;
    }
    __syncthreads();

    const int tx = tid & 31, ty = tid >> 5;
    float match3 = 0.f, ent3 = 0.f, var3 = 0.f, maj3 = 0.f;
    float match5 = 0.f, ent5 = 0.f, var5 = 0.f, maj5 = 0.f;

#pragma unroll 1
    for (int c = 0; c < NC; c++) {
        const float* Pc = &P[c * EY * EX + ty * EX + tx];
        float s3 = 0.f, q3 = 0.f, s5 = 0.f, q5 = 0.f;
#pragma unroll
        for (int dr = 0; dr < 5; dr++) {
#pragma unroll
            for (int dc = 0; dc < 5; dc++) {
                float p = Pc[dr * EX + dc];
                s5 += p; q5 += p * p;
                if (dr >= 1 && dr <= 3 && dc >= 1 && dc <= 3) { s3 += p; q3 += p * p; }
            }
        }
        float pcen = Pc[2 * EX + 2];
        match3 += pcen * (s3 - pcen);
        match5 += pcen * (s5 - pcen);
        maj3 = fmaxf(maj3, s3);
        maj5 = fmaxf(maj5, s5);
        float pb3 = s3 * (1.f / 9.f),  pb5 = s5 * (1.f / 25.f);
        float pc3 = fmaxf(pb3, 1e-8f), pc5 = fmaxf(pb5, 1e-8f);
        ent3 -= pc3 * __logf(pc3);
        ent5 -= pc5 * __logf(pc5);
        var3 += q3 * (1.f / 9.f)  - pb3 * pb3;
        var5 += q5 * (1.f / 25.f) - pb5 * pb5;
    }

    const float INV_LOGC = 0.434294481903252f; // 1/ln(10)
    float f[8];
    f[0] = match3 * (1.f / 8.f);
    f[1] = maj3 * (1.f / 9.f);
    f[2] = 1.f - ent3 * INV_LOGC;
    f[3] = var3;
    f[4] = match5 * (1.f / 24.f);
    f[5] = maj5 * (1.f / 25.f);
    f[6] = 1.f - ent5 * INV_LOGC;
    f[7] = var5;

    // h = W1 f + b1 ; write to scratch ; accumulate per-group stats
    const int pix = (r0 + ty) * Ww + (c0 + tx);
    float* hb = g_h + (size_t)b * D64 * HW + pix;
    float gsum[8], gsq[8];
#pragma unroll
    for (int g = 0; g < 8; g++) { gsum[g] = 0.f; gsq[g] = 0.f; }
#pragma unroll
    for (int d = 0; d < 64; d++) {
        const float4 wa = *(const float4*)&w1s[d * 8];
        const float4 wb = *(const float4*)&w1s[d * 8 + 4];
        float acc = b1s[d];
        acc += wa.x * f[0] + wa.y * f[1] + wa.z * f[2] + wa.w * f[3];
        acc += wb.x * f[4] + wb.y * f[5] + wb.z * f[6] + wb.w * f[7];
        hb[(size_t)d * HW] = acc;
        gsum[d >> 3] += acc;
        gsq[d >> 3]  += acc * acc;
    }
    // warp reduce -> smem -> global atomics
#pragma unroll
    for (int g = 0; g < 8; g++) {
        float a = gsum[g], q = gsq[g];
#pragma unroll
        for (int o = 16; o; o >>= 1) {
            a += __shfl_xor_sync(0xffffffffu, a, o);
            q += __shfl_xor_sync(0xffffffffu, q, o);
        }
        if ((tid & 31) == 0) { atomicAdd(&sstat[2 * g], a); atomicAdd(&sstat[2 * g + 1], q); }
    }
    __syncthreads();
    if (tid < 16) atomicAdd(&g_stats[b * 16 + tid], sstat[tid]);
}

// ---------------- K2: finalize GN stats ----------------
__global__ void k_stats() {
    int i = threadIdx.x;
    if (i < 64) {
        const float invN = 1.f / (8.f * (float)HW);
        float s  = g_stats[2 * i];
        float ss = g_stats[2 * i + 1];
        float mean = s * invN;
        float var  = ss * invN - mean * mean;
        g_mean[i] = mean;
        g_rstd[i] = rsqrtf(var + 1e-5f);
    }
}

// ---------------- K3: GN + GELU + W2 (f32x2 packed GEMM) ----------------
__device__ __forceinline__ u64 pack2(float x, float y) {
    u64 r;
    asm("mov.b64 %0, {%1, %2};" : "=l"(r) : "f"(x), "f"(y));
    return r;
}
__device__ __forceinline__ u64 fma2(u64 a, u64 b, u64 c) {
    u64 d;
    asm("fma.rn.f32x2 %0, %1, %2, %3;" : "=l"(d) : "l"(a), "l"(b), "l"(c));
    return d;
}

// branch-free erf-GELU (A&S 7.1.26, abs err ~1.5e-7)
__device__ __forceinline__ float gelu_fast(float h) {
    float z = h * 0.70710678118f;
    float x = fabsf(z);
    float t = __fdividef(1.f, fmaf(0.3275911f, x, 1.f));
    float p = fmaf(1.061405429f, t, -1.453152027f);
    p = fmaf(p, t, 1.421413741f);
    p = fmaf(p, t, -0.284496736f);
    p = fmaf(p, t, 0.254829592f);
    p = p * t;
    float e = __expf(-x * x);
    float er = fmaf(-p, e, 1.f);          // erf(|z|)
    er = copysignf(er, z);
    return 0.5f * h * (1.f + er);
}

#define SMEM3 (64 * 256 * 4 + 4096 * 8 + 208 * 4)

__global__ __launch_bounds__(256, 2) void k_out(const float* __restrict__ gnw,
                                                const float* __restrict__ gnb,
                                                const float* __restrict__ W2,
                                                const float* __restrict__ b2,
                                                float* __restrict__ out) {
    extern __shared__ char sraw[];
    float* G = (float*)sraw;                               // [64][256]
    u64* w2p = (u64*)(sraw + 64 * 256 * 4);                // [d][d2] {w,w}
    float* sp = (float*)(sraw + 64 * 256 * 4 + 4096 * 8);  // mean/rstd/gnw/gnb/b2

    const int b  = blockIdx.y;
    const int p0 = blockIdx.x * 256;
    const int t  = threadIdx.x;

    if (t < 64) { sp[16 + t] = gnw[t]; sp[80 + t] = gnb[t]; sp[144 + t] = b2[t]; }
    if (t < 8)  { sp[t] = g_mean[b * 8 + t]; sp[8 + t] = g_rstd[b * 8 + t]; }
    __syncthreads();

    // ---- w2p pack + GN + GELU into smem (overlapped window) ----
    for (int i = t; i < 4096; i += 256) {
        float w = W2[i];                              // W2[d2][d]
        w2p[(i & 63) * 64 + (i >> 6)] = pack2(w, w);  // transposed [d][d2]
    }
    {
        const float* hb = g_h + (size_t)b * D64 * HW + p0;
        const int dq = t >> 6;          // 0..3  (warp-uniform)
        const int px = (t & 63) * 4;    // 0..252
#pragma unroll
        for (int half = 0; half < 2; half++) {
            float4 hv[8];
#pragma unroll
            for (int j = 0; j < 8; j++) {
                int d = (half * 8 + j) * 4 + dq;
                hv[j] = *(const float4*)&hb[(size_t)d * HW + px];
            }
#pragma unroll
            for (int j = 0; j < 8; j++) {
                int d = (half * 8 + j) * 4 + dq;
                int g = d >> 3;
                float a = sp[8 + g] * sp[16 + d];
                float c = sp[80 + d] - sp[g] * a;
                float4 r;
                r.x = gelu_fast(fmaf(hv[j].x, a, c));
                r.y = gelu_fast(fmaf(hv[j].y, a, c));
                r.z = gelu_fast(fmaf(hv[j].z, a, c));
                r.w = gelu_fast(fmaf(hv[j].w, a, c));
                *(float4*)&G[d * 256 + px] = r;
            }
        }
    }
    __syncthreads();

    // ---- out[64][256] = W2 @ G : 8 d2 x 8 px (4 pairs) per thread ----
    const int d2b = (t >> 5) * 8;
    const int p4  = (t & 31) * 4;      // pixels p4..p4+3 and p4+128..p4+131
    u64 acc[8][4];
#pragma unroll
    for (int i = 0; i < 8; i++) {
        float bv = sp[144 + d2b + i];
        u64 bp = pack2(bv, bv);
#pragma unroll
        for (int j = 0; j < 4; j++) acc[i][j] = bp;
    }

    const float* Gp = G + p4;
    const u64*   wp = w2p + d2b;
#pragma unroll 4
    for (int d = 0; d < 64; d++) {
        ulonglong2 ga = *(const ulonglong2*)(Gp);
        ulonglong2 gb = *(const ulonglong2*)(Gp + 128);
        ulonglong2 w01 = *(const ulonglong2*)(wp);
        ulonglong2 w23 = *(const ulonglong2*)(wp + 2);
        ulonglong2 w45 = *(const ulonglong2*)(wp + 4);
        ulonglong2 w67 = *(const ulonglong2*)(wp + 6);
        u64 wv[8];
        wv[0] = w01.x; wv[1] = w01.y; wv[2] = w23.x; wv[3] = w23.y;
        wv[4] = w45.x; wv[5] = w45.y; wv[6] = w67.x; wv[7] = w67.y;
#pragma unroll
        for (int i = 0; i < 8; i++) {
            acc[i][0] = fma2(wv[i], ga.x, acc[i][0]);
            acc[i][1] = fma2(wv[i], ga.y, acc[i][1]);
            acc[i][2] = fma2(wv[i], gb.x, acc[i][2]);
            acc[i][3] = fma2(wv[i], gb.y, acc[i][3]);
        }
        Gp += 256; wp += 64;
    }

    float* ob = out + (size_t)b * D64 * HW + p0;
#pragma unroll
    for (int i = 0; i < 8; i++) {
        size_t base = (size_t)(d2b + i) * HW;
        ulonglong2 s0; s0.x = acc[i][0]; s0.y = acc[i][1];
        ulonglong2 s1; s1.x = acc[i][2]; s1.y = acc[i][3];
        *(ulonglong2*)&ob[base + p4]       = s0;
        *(ulonglong2*)&ob[base + p4 + 128] = s1;
    }
}

// ---------------- launch ----------------
extern "C" void kernel_launch(void* const* d_in, const int* in_sizes, int n_in,
                              void* d_out, int out_size) {
    const float* x   = (const float*)d_in[0];
    const float* W1  = (const float*)d_in[1];
    const float* b1  = (const float*)d_in[2];
    const float* gnw = (const float*)d_in[3];
    const float* gnb = (const float*)d_in[4];
    const float* W2  = (const float*)d_in[5];
    const float* b2  = (const float*)d_in[6];
    float* out = (float*)d_out;

    k_zero<<<1, 128>>>();

    dim3 g1(Ww / TLX, Hh / TLY, BATCH);   // 12 x 48 x 8
    k_feat<<<g1, 256>>>(x, W1, b1);

    k_stats<<<1, 64>>>();

    cudaFuncSetAttribute(k_out, cudaFuncAttributeMaxDynamicSharedMemorySize, SMEM3);
    dim3 g3(HW / 256, BATCH);             // 576 x 8
    k_out<<<g3, 256, SMEM3>>>(gnw, gnb, W2, b2, out);
}

// round 7
// speedup vs baseline: 1.3862x; 1.1100x over previous
#include <cuda_runtime.h>
#include <math.h>
#include <stdint.h>

#define Hh 384
#define Ww 384
#define NC 10
#define HW (384*384)
#define BATCH 8
#define D64 64

typedef unsigned long long u64;

// ---- scratch (static device globals: allocation-free) ----
__device__ float g_h[(size_t)BATCH * D64 * HW];   // 302 MB intermediate h
__device__ float g_stats[128];                    // [b][g][{sum,sumsq}]
__device__ float g_mean[64];
__device__ float g_rstd[64];

// ---------------- K0: zero stats ----------------
__global__ void k_zero() { g_stats[threadIdx.x] = 0.f; }

// ---------------- K1: softmax + neighbor features + W1 + stat partials ----
#define TLX 32
#define TLY 8
#define EX 36
#define EY 12

__global__ __launch_bounds__(256) void k_feat(const float* __restrict__ x,
                                              const float* __restrict__ W1,
                                              const float* __restrict__ b1) {
    __shared__ float P[NC * EY * EX];          // softmax probs, tile + 2px halo
    __shared__ __align__(16) float w1s[512];
    __shared__ float b1s[64];
    __shared__ float sstat[16];

    const int b  = blockIdx.z;
    const int r0 = blockIdx.y * TLY, c0 = blockIdx.x * TLX;
    const int tid = threadIdx.x;

    for (int i = tid; i < 512; i += 256) w1s[i] = W1[i];
    if (tid < 64)  b1s[tid] = b1[tid];
    if (tid < 16)  sstat[tid] = 0.f;

    const float* xb = x + (size_t)b * NC * HW;
    for (int i = tid; i < EX * EY; i += 256) {
        int er = i / EX, ec = i % EX;
        int gr = min(max(r0 + er - 2, 0), Hh - 1);
        int gc = min(max(c0 + ec - 2, 0), Ww - 1);
        const float* xp = xb + gr * Ww + gc;
        float v[NC];
        float m = -1e30f;
#pragma unroll
        for (int c = 0; c < NC; c++) { v[c] = xp[(size_t)c * HW]; m = fmaxf(m, v[c]); }
        float s = 0.f;
#pragma unroll
        for (int c = 0; c < NC; c++) { v[c] = __expf(v[c] - m); s += v[c]; }
        float inv = 1.f / s;
#pragma unroll
        for (int c = 0; c < NC; c++) P[c * EY * EX + i] = v[c] * inv;
    }
    __syncthreads();

    const int tx = tid & 31, ty = tid >> 5;
    float match3 = 0.f, ent3 = 0.f, var3 = 0.f, maj3 = 0.f;
    float match5 = 0.f, ent5 = 0.f, var5 = 0.f, maj5 = 0.f;

#pragma unroll 1
    for (int c = 0; c < NC; c++) {
        const float* Pc = &P[c * EY * EX + ty * EX + tx];
        float s3 = 0.f, q3 = 0.f, s5 = 0.f, q5 = 0.f;
#pragma unroll
        for (int dr = 0; dr < 5; dr++) {
#pragma unroll
            for (int dc = 0; dc < 5; dc++) {
                float p = Pc[dr * EX + dc];
                s5 += p; q5 += p * p;
                if (dr >= 1 && dr <= 3 && dc >= 1 && dc <= 3) { s3 += p; q3 += p * p; }
            }
        }
        float pcen = Pc[2 * EX + 2];
        match3 += pcen * (s3 - pcen);
        match5 += pcen * (s5 - pcen);
        maj3 = fmaxf(maj3, s3);
        maj5 = fmaxf(maj5, s5);
        float pb3 = s3 * (1.f / 9.f),  pb5 = s5 * (1.f / 25.f);
        float pc3 = fmaxf(pb3, 1e-8f), pc5 = fmaxf(pb5, 1e-8f);
        ent3 -= pc3 * __logf(pc3);
        ent5 -= pc5 * __logf(pc5);
        var3 += q3 * (1.f / 9.f)  - pb3 * pb3;
        var5 += q5 * (1.f / 25.f) - pb5 * pb5;
    }

    const float INV_LOGC = 0.434294481903252f; // 1/ln(10)
    float f[8];
    f[0] = match3 * (1.f / 8.f);
    f[1] = maj3 * (1.f / 9.f);
    f[2] = 1.f - ent3 * INV_LOGC;
    f[3] = var3;
    f[4] = match5 * (1.f / 24.f);
    f[5] = maj5 * (1.f / 25.f);
    f[6] = 1.f - ent5 * INV_LOGC;
    f[7] = var5;

    const int pix = (r0 + ty) * Ww + (c0 + tx);
    float* hb = g_h + (size_t)b * D64 * HW + pix;
    float gsum[8], gsq[8];
#pragma unroll
    for (int g = 0; g < 8; g++) { gsum[g] = 0.f; gsq[g] = 0.f; }
#pragma unroll
    for (int d = 0; d < 64; d++) {
        const float4 wa = *(const float4*)&w1s[d * 8];
        const float4 wb = *(const float4*)&w1s[d * 8 + 4];
        float acc = b1s[d];
        acc += wa.x * f[0] + wa.y * f[1] + wa.z * f[2] + wa.w * f[3];
        acc += wb.x * f[4] + wb.y * f[5] + wb.z * f[6] + wb.w * f[7];
        hb[(size_t)d * HW] = acc;
        gsum[d >> 3] += acc;
        gsq[d >> 3]  += acc * acc;
    }
#pragma unroll
    for (int g = 0; g < 8; g++) {
        float a = gsum[g], q = gsq[g];
#pragma unroll
        for (int o = 16; o; o >>= 1) {
            a += __shfl_xor_sync(0xffffffffu, a, o);
            q += __shfl_xor_sync(0xffffffffu, q, o);
        }
        if ((tid & 31) == 0) { atomicAdd(&sstat[2 * g], a); atomicAdd(&sstat[2 * g + 1], q); }
    }
    __syncthreads();
    if (tid < 16) atomicAdd(&g_stats[b * 16 + tid], sstat[tid]);
}

// ---------------- K2: finalize GN stats ----------------
__global__ void k_stats() {
    int i = threadIdx.x;
    if (i < 64) {
        const float invN = 1.f / (8.f * (float)HW);
        float s  = g_stats[2 * i];
        float ss = g_stats[2 * i + 1];
        float mean = s * invN;
        float var  = ss * invN - mean * mean;
        g_mean[i] = mean;
        g_rstd[i] = rsqrtf(var + 1e-5f);
    }
}

// ---------------- K3: GN + GELU + W2 (f32x2, d2-paired, 3 CTAs/SM) -------
__device__ __forceinline__ u64 pack2(float x, float y) {
    u64 r;
    asm("mov.b64 %0, {%1, %2};" : "=l"(r) : "f"(x), "f"(y));
    return r;
}
__device__ __forceinline__ u64 fma2(u64 a, u64 b, u64 c) {
    u64 d;
    asm("fma.rn.f32x2 %0, %1, %2, %3;" : "=l"(d) : "l"(a), "l"(b), "l"(c));
    return d;
}

// branch-free erf-GELU (A&S 7.1.26, abs err ~1.5e-7)
__device__ __forceinline__ float gelu_fast(float h) {
    float z = h * 0.70710678118f;
    float x = fabsf(z);
    float t = __fdividef(1.f, fmaf(0.3275911f, x, 1.f));
    float p = fmaf(1.061405429f, t, -1.453152027f);
    p = fmaf(p, t, 1.421413741f);
    p = fmaf(p, t, -0.284496736f);
    p = fmaf(p, t, 0.254829592f);
    p = p * t;
    float e = __expf(-x * x);
    float er = fmaf(-p, e, 1.f);
    er = copysignf(er, z);
    return 0.5f * h * (1.f + er);
}

// smem: G [64][128] f32 = 32KB ; w2i [64][32] u64 = 16KB ; sp 768B
#define G_OFF  0
#define W_OFF  32768
#define SP_OFF 49152
#define SMEM3  (49152 + 768)

__global__ void __launch_bounds__(256, 3) k_out(const float* __restrict__ gnw,
                                                const float* __restrict__ gnb,
                                                const float* __restrict__ W2,
                                                const float* __restrict__ b2,
                                                float* __restrict__ out) {
    extern __shared__ char s[];
    float* G  = (float*)(s + G_OFF);     // [d][px] 64 x 128 (also W2 staging)
    u64* w2i  = (u64*)(s + W_OFF);       // [d][pair] 64 x 32, pair p = {W2[2p][d], W2[2p+1][d]}
    float* sp = (float*)(s + SP_OFF);    // a[64], c[64], b2[64]

    const int b  = blockIdx.y;
    const int p0 = blockIdx.x * 128;
    const int t  = threadIdx.x;

    if (t < 64) {
        int g = t >> 3;
        float a = g_rstd[b * 8 + g] * gnw[t];
        sp[t]       = a;
        sp[64 + t]  = gnb[t] - g_mean[b * 8 + g] * a;
        sp[128 + t] = b2[t];
    }
    // ---- stage W2 coalesced into G area, then build pair table ----
    {
        float* raw = G;                          // 4096 floats, reused before GN fill
        for (int i = t; i < 1024; i += 256)
            *(float4*)&raw[i * 4] = *(const float4*)&W2[i * 4];
        __syncthreads();
        for (int i = t; i < 2048; i += 256) {
            int p = i >> 6, d = i & 63;          // lanes vary d -> conflict-free LDS
            w2i[d * 32 + p] = pack2(raw[(2 * p) * 64 + d], raw[(2 * p + 1) * 64 + d]);
        }
    }
    __syncthreads();

    // ---- GN + GELU into G: thread = 4 px x 8 d ----
    {
        const float* hb = g_h + (size_t)b * D64 * HW + p0;
        const int pxq  = (t & 31) * 4;
        const int dblk = t >> 5;                // 0..7
        float4 hv[8];
#pragma unroll
        for (int j = 0; j < 8; j++)
            hv[j] = *(const float4*)&hb[(size_t)(dblk * 8 + j) * HW + pxq];
#pragma unroll
        for (int j = 0; j < 8; j++) {
            int d = dblk * 8 + j;
            float a = sp[d], c = sp[64 + d];
            float4 r;
            r.x = gelu_fast(fmaf(hv[j].x, a, c));
            r.y = gelu_fast(fmaf(hv[j].y, a, c));
            r.z = gelu_fast(fmaf(hv[j].z, a, c));
            r.w = gelu_fast(fmaf(hv[j].w, a, c));
            *(float4*)&G[d * 128 + pxq] = r;
        }
    }
    __syncthreads();

    // ---- GEMM: thread = pixels {px, px+64} x 16 d2 (8 f32x2 pairs) ----
    const int px  = t & 63;
    const int pb8 = (t >> 6) * 8;               // first d2-pair index
    u64 acc0[8], acc1[8];
#pragma unroll
    for (int i = 0; i < 8; i++) {
        u64 bp = pack2(sp[128 + 2 * (pb8 + i)], sp[128 + 2 * (pb8 + i) + 1]);
        acc0[i] = bp;
        acc1[i] = bp;
    }

    const float* Gp = G + px;
    const u64*   wp = w2i + pb8;
#pragma unroll 4
    for (int d = 0; d < 64; d++) {
        float ga = Gp[0];
        float gb = Gp[64];
        u64 gpa = pack2(ga, ga);
        u64 gpb = pack2(gb, gb);
        ulonglong2 w01 = *(const ulonglong2*)(wp);
        ulonglong2 w23 = *(const ulonglong2*)(wp + 2);
        ulonglong2 w45 = *(const ulonglong2*)(wp + 4);
        ulonglong2 w67 = *(const ulonglong2*)(wp + 6);
        acc0[0] = fma2(w01.x, gpa, acc0[0]);  acc1[0] = fma2(w01.x, gpb, acc1[0]);
        acc0[1] = fma2(w01.y, gpa, acc0[1]);  acc1[1] = fma2(w01.y, gpb, acc1[1]);
        acc0[2] = fma2(w23.x, gpa, acc0[2]);  acc1[2] = fma2(w23.x, gpb, acc1[2]);
        acc0[3] = fma2(w23.y, gpa, acc0[3]);  acc1[3] = fma2(w23.y, gpb, acc1[3]);
        acc0[4] = fma2(w45.x, gpa, acc0[4]);  acc1[4] = fma2(w45.x, gpb, acc1[4]);
        acc0[5] = fma2(w45.y, gpa, acc0[5]);  acc1[5] = fma2(w45.y, gpb, acc1[5]);
        acc0[6] = fma2(w67.x, gpa, acc0[6]);  acc1[6] = fma2(w67.x, gpb, acc1[6]);
        acc0[7] = fma2(w67.y, gpa, acc0[7]);  acc1[7] = fma2(w67.y, gpb, acc1[7]);
        Gp += 128; wp += 32;
    }

    // ---- stores: 32 coalesced STG.32 ----
    float* ob = out + (size_t)b * D64 * HW + p0 + px;
#pragma unroll
    for (int i = 0; i < 8; i++) {
        int d2 = 2 * (pb8 + i);
        float2 a0 = *(float2*)&acc0[i];   // (out[d2][px], out[d2+1][px])
        float2 a1 = *(float2*)&acc1[i];   // (out[d2][px+64], out[d2+1][px+64])
        ob[(size_t)d2 * HW]            = a0.x;
        ob[(size_t)(d2 + 1) * HW]      = a0.y;
        ob[(size_t)d2 * HW + 64]       = a1.x;
        ob[(size_t)(d2 + 1) * HW + 64] = a1.y;
    }
}

// ---------------- launch ----------------
extern "C" void kernel_launch(void* const* d_in, const int* in_sizes, int n_in,
                              void* d_out, int out_size) {
    const float* x   = (const float*)d_in[0];
    const float* W1  = (const float*)d_in[1];
    const float* b1  = (const float*)d_in[2];
    const float* gnw = (const float*)d_in[3];
    const float* gnb = (const float*)d_in[4];
    const float* W2  = (const float*)d_in[5];
    const float* b2  = (const float*)d_in[6];
    float* out = (float*)d_out;

    k_zero<<<1, 128>>>();

    dim3 g1(Ww / TLX, Hh / TLY, BATCH);   // 12 x 48 x 8
    k_feat<<<g1, 256>>>(x, W1, b1);

    k_stats<<<1, 64>>>();

    cudaFuncSetAttribute(k_out, cudaFuncAttributeMaxDynamicSharedMemorySize, SMEM3);
    dim3 g3(HW / 128, BATCH);             // 1152 x 8
    k_out<<<g3, 256, SMEM3>>>(gnw, gnb, W2, b2, out);
}

// round 8
// speedup vs baseline: 1.5525x; 1.1200x over previous
#include <cuda_runtime.h>
#include <math.h>
#include <stdint.h>

#define Hh 384
#define Ww 384
#define NC 10
#define HW (384*384)
#define BATCH 8
#define D64 64

typedef unsigned long long u64;

// ---- scratch (static device globals: allocation-free) ----
__device__ float g_h[(size_t)BATCH * D64 * HW];   // 302 MB intermediate h
__device__ float g_stats[128];                    // [b][g][{sum,sumsq}]
__device__ float g_mean[64];
__device__ float g_rstd[64];

// ---------------- K0: zero stats ----------------
__global__ void k_zero() { g_stats[threadIdx.x] = 0.f; }

// ---------------- K1: softmax + neighbor features + W1 + stat partials ----
#define TLX 32
#define TLY 8
#define EX 36
#define EY 12

__global__ __launch_bounds__(256) void k_feat(const float* __restrict__ x,
                                              const float* __restrict__ W1,
                                              const float* __restrict__ b1) {
    __shared__ float P[NC * EY * EX];          // softmax probs, tile + 2px halo
    __shared__ __align__(16) float w1s[512];
    __shared__ float b1s[64];
    __shared__ float sstat[16];

    const int b  = blockIdx.z;
    const int r0 = blockIdx.y * TLY, c0 = blockIdx.x * TLX;
    const int tid = threadIdx.x;

    for (int i = tid; i < 512; i += 256) w1s[i] = W1[i];
    if (tid < 64)  b1s[tid] = b1[tid];
    if (tid < 16)  sstat[tid] = 0.f;

    const float* xb = x + (size_t)b * NC * HW;
    for (int i = tid; i < EX * EY; i += 256) {
        int er = i / EX, ec = i % EX;
        int gr = min(max(r0 + er - 2, 0), Hh - 1);
        int gc = min(max(c0 + ec - 2, 0), Ww - 1);
        const float* xp = xb + gr * Ww + gc;
        float v[NC];
        float m = -1e30f;
#pragma unroll
        for (int c = 0; c < NC; c++) { v[c] = xp[(size_t)c * HW]; m = fmaxf(m, v[c]); }
        float s = 0.f;
#pragma unroll
        for (int c = 0; c < NC; c++) { v[c] = __expf(v[c] - m); s += v[c]; }
        float inv = 1.f / s;
#pragma unroll
        for (int c = 0; c < NC; c++) P[c * EY * EX + i] = v[c] * inv;
    }
    __syncthreads();

    const int tx = tid & 31, ty = tid >> 5;
    float match3 = 0.f, ent3 = 0.f, var3 = 0.f, maj3 = 0.f;
    float match5 = 0.f, ent5 = 0.f, var5 = 0.f, maj5 = 0.f;

#pragma unroll 1
    for (int c = 0; c < NC; c++) {
        const float* Pc = &P[c * EY * EX + ty * EX + tx];
        float s3 = 0.f, q3 = 0.f, s5 = 0.f, q5 = 0.f;
#pragma unroll
        for (int dr = 0; dr < 5; dr++) {
#pragma unroll
            for (int dc = 0; dc < 5; dc++) {
                float p = Pc[dr * EX + dc];
                s5 += p; q5 += p * p;
                if (dr >= 1 && dr <= 3 && dc >= 1 && dc <= 3) { s3 += p; q3 += p * p; }
            }
        }
        float pcen = Pc[2 * EX + 2];
        match3 += pcen * (s3 - pcen);
        match5 += pcen * (s5 - pcen);
        maj3 = fmaxf(maj3, s3);
        maj5 = fmaxf(maj5, s5);
        float pb3 = s3 * (1.f / 9.f),  pb5 = s5 * (1.f / 25.f);
        float pc3 = fmaxf(pb3, 1e-8f), pc5 = fmaxf(pb5, 1e-8f);
        ent3 -= pc3 * __logf(pc3);
        ent5 -= pc5 * __logf(pc5);
        var3 += q3 * (1.f / 9.f)  - pb3 * pb3;
        var5 += q5 * (1.f / 25.f) - pb5 * pb5;
    }

    const float INV_LOGC = 0.434294481903252f; // 1/ln(10)
    float f[8];
    f[0] = match3 * (1.f / 8.f);
    f[1] = maj3 * (1.f / 9.f);
    f[2] = 1.f - ent3 * INV_LOGC;
    f[3] = var3;
    f[4] = match5 * (1.f / 24.f);
    f[5] = maj5 * (1.f / 25.f);
    f[6] = 1.f - ent5 * INV_LOGC;
    f[7] = var5;

    const int pix = (r0 + ty) * Ww + (c0 + tx);
    float* hb = g_h + (size_t)b * D64 * HW + pix;
    float gsum[8], gsq[8];
#pragma unroll
    for (int g = 0; g < 8; g++) { gsum[g] = 0.f; gsq[g] = 0.f; }
#pragma unroll
    for (int d = 0; d < 64; d++) {
        const float4 wa = *(const float4*)&w1s[d * 8];
        const float4 wb = *(const float4*)&w1s[d * 8 + 4];
        float acc = b1s[d];
        acc += wa.x * f[0] + wa.y * f[1] + wa.z * f[2] + wa.w * f[3];
        acc += wb.x * f[4] + wb.y * f[5] + wb.z * f[6] + wb.w * f[7];
        hb[(size_t)d * HW] = acc;
        gsum[d >> 3] += acc;
        gsq[d >> 3]  += acc * acc;
    }
#pragma unroll
    for (int g = 0; g < 8; g++) {
        float a = gsum[g], q = gsq[g];
#pragma unroll
        for (int o = 16; o; o >>= 1) {
            a += __shfl_xor_sync(0xffffffffu, a, o);
            q += __shfl_xor_sync(0xffffffffu, q, o);
        }
        if ((tid & 31) == 0) { atomicAdd(&sstat[2 * g], a); atomicAdd(&sstat[2 * g + 1], q); }
    }
    __syncthreads();
    if (tid < 16) atomicAdd(&g_stats[b * 16 + tid], sstat[tid]);
}

// ---------------- K2: finalize GN stats ----------------
__global__ void k_stats() {
    int i = threadIdx.x;
    if (i < 64) {
        const float invN = 1.f / (8.f * (float)HW);
        float s  = g_stats[2 * i];
        float ss = g_stats[2 * i + 1];
        float mean = s * invN;
        float var  = ss * invN - mean * mean;
        g_mean[i] = mean;
        g_rstd[i] = rsqrtf(var + 1e-5f);
    }
}

// -------- K3: GN + GELU + W2 (f32x2, X=128px/Y=4pairs per warp) ----------
__device__ __forceinline__ u64 pack2(float x, float y) {
    u64 r;
    asm("mov.b64 %0, {%1, %2};" : "=l"(r) : "f"(x), "f"(y));
    return r;
}
__device__ __forceinline__ u64 fma2(u64 a, u64 b, u64 c) {
    u64 d;
    asm("fma.rn.f32x2 %0, %1, %2, %3;" : "=l"(d) : "l"(a), "l"(b), "l"(c));
    return d;
}

// branch-free erf-GELU (A&S 7.1.26, abs err ~1.5e-7)
__device__ __forceinline__ float gelu_fast(float h) {
    float z = h * 0.70710678118f;
    float x = fabsf(z);
    float t = __fdividef(1.f, fmaf(0.3275911f, x, 1.f));
    float p = fmaf(1.061405429f, t, -1.453152027f);
    p = fmaf(p, t, 1.421413741f);
    p = fmaf(p, t, -0.284496736f);
    p = fmaf(p, t, 0.254829592f);
    p = p * t;
    float e = __expf(-x * x);
    float er = fmaf(-p, e, 1.f);
    er = copysignf(er, z);
    return 0.5f * h * (1.f + er);
}

// smem: G [64][128] f32 = 32KB ; w2i [64][32] u64 = 16KB ; sp 768B
#define G_OFF  0
#define W_OFF  32768
#define SP_OFF 49152
#define SMEM3  (49152 + 768)

__global__ void __launch_bounds__(256, 3) k_out(const float* __restrict__ gnw,
                                                const float* __restrict__ gnb,
                                                const float* __restrict__ W2,
                                                const float* __restrict__ b2,
                                                float* __restrict__ out) {
    extern __shared__ char s[];
    float* G  = (float*)(s + G_OFF);     // [d][px] 64 x 128 (also W2 staging)
    u64* w2i  = (u64*)(s + W_OFF);       // [d][pair] 64 x 32, pair p = {W2[2p][d], W2[2p+1][d]}
    float* sp = (float*)(s + SP_OFF);    // a[64], c[64], b2[64]

    const int b  = blockIdx.y;
    const int p0 = blockIdx.x * 128;
    const int t  = threadIdx.x;

    if (t < 64) {
        int g = t >> 3;
        float a = g_rstd[b * 8 + g] * gnw[t];
        sp[t]       = a;
        sp[64 + t]  = gnb[t] - g_mean[b * 8 + g] * a;
        sp[128 + t] = b2[t];
    }
    // ---- stage W2 coalesced into G area, then build pair table ----
    {
        float* raw = G;                          // 4096 floats, reused before GN fill
        for (int i = t; i < 1024; i += 256)
            *(float4*)&raw[i * 4] = *(const float4*)&W2[i * 4];
        __syncthreads();
        for (int i = t; i < 2048; i += 256) {
            int p = i >> 6, d = i & 63;          // lanes vary d -> conflict-free LDS
            w2i[d * 32 + p] = pack2(raw[(2 * p) * 64 + d], raw[(2 * p + 1) * 64 + d]);
        }
    }
    __syncthreads();

    // ---- GN + GELU into G: thread = 4 px x 8 d ----
    {
        const float* hb = g_h + (size_t)b * D64 * HW + p0;
        const int pxq  = (t & 31) * 4;
        const int dblk = t >> 5;                // 0..7
        float4 hv[8];
#pragma unroll
        for (int j = 0; j < 8; j++)
            hv[j] = *(const float4*)&hb[(size_t)(dblk * 8 + j) * HW + pxq];
#pragma unroll
        for (int j = 0; j < 8; j++) {
            int d = dblk * 8 + j;
            float a = sp[d], c = sp[64 + d];
            float4 r;
            r.x = gelu_fast(fmaf(hv[j].x, a, c));
            r.y = gelu_fast(fmaf(hv[j].y, a, c));
            r.z = gelu_fast(fmaf(hv[j].z, a, c));
            r.w = gelu_fast(fmaf(hv[j].w, a, c));
            *(float4*)&G[d * 128 + pxq] = r;
        }
    }
    __syncthreads();

    // ---- GEMM: warp = 128 px x 8 d2 ; thread = 4 px x 4 d2-pairs ----
    const int lane = t & 31;
    const int wrp  = t >> 5;                    // 0..7 -> d2 base 8*wrp
    const int pxb  = lane * 4;
    u64 acc[4][4];                              // [pair][px]
#pragma unroll
    for (int p = 0; p < 4; p++) {
        u64 bp = pack2(sp[128 + 8 * wrp + 2 * p], sp[128 + 8 * wrp + 2 * p + 1]);
#pragma unroll
        for (int x = 0; x < 4; x++) acc[p][x] = bp;
    }

    const float* Gp = G + pxb;
    const u64*   wp = w2i + 4 * wrp;
#pragma unroll 4
    for (int d = 0; d < 64; d++) {
        float4 gv = *(const float4*)Gp;         // 4 px, per-lane LDS.128
        u64 g0 = pack2(gv.x, gv.x);
        u64 g1 = pack2(gv.y, gv.y);
        u64 g2 = pack2(gv.z, gv.z);
        u64 g3 = pack2(gv.w, gv.w);
        ulonglong2 wa = *(const ulonglong2*)(wp);       // pairs 0,1 (uniform)
        ulonglong2 wb = *(const ulonglong2*)(wp + 2);   // pairs 2,3 (uniform)
        acc[0][0] = fma2(wa.x, g0, acc[0][0]);
        acc[0][1] = fma2(wa.x, g1, acc[0][1]);
        acc[0][2] = fma2(wa.x, g2, acc[0][2]);
        acc[0][3] = fma2(wa.x, g3, acc[0][3]);
        acc[1][0] = fma2(wa.y, g0, acc[1][0]);
        acc[1][1] = fma2(wa.y, g1, acc[1][1]);
        acc[1][2] = fma2(wa.y, g2, acc[1][2]);
        acc[1][3] = fma2(wa.y, g3, acc[1][3]);
        acc[2][0] = fma2(wb.x, g0, acc[2][0]);
        acc[2][1] = fma2(wb.x, g1, acc[2][1]);
        acc[2][2] = fma2(wb.x, g2, acc[2][2]);
        acc[2][3] = fma2(wb.x, g3, acc[2][3]);
        acc[3][0] = fma2(wb.y, g0, acc[3][0]);
        acc[3][1] = fma2(wb.y, g1, acc[3][1]);
        acc[3][2] = fma2(wb.y, g2, acc[3][2]);
        acc[3][3] = fma2(wb.y, g3, acc[3][3]);
        Gp += 128; wp += 32;
    }

    // ---- stores: 8 coalesced STG.128 per thread ----
    float* ob = out + (size_t)b * D64 * HW + p0 + pxb;
#pragma unroll
    for (int p = 0; p < 4; p++) {
        int d2 = 8 * wrp + 2 * p;
        float2 a0 = *(float2*)&acc[p][0];
        float2 a1 = *(float2*)&acc[p][1];
        float2 a2 = *(float2*)&acc[p][2];
        float2 a3 = *(float2*)&acc[p][3];
        float4 lo; lo.x = a0.x; lo.y = a1.x; lo.z = a2.x; lo.w = a3.x;
        float4 hi; hi.x = a0.y; hi.y = a1.y; hi.z = a2.y; hi.w = a3.y;
        *(float4*)&ob[(size_t)d2 * HW]       = lo;
        *(float4*)&ob[(size_t)(d2 + 1) * HW] = hi;
    }
}

// ---------------- launch ----------------
extern "C" void kernel_launch(void* const* d_in, const int* in_sizes, int n_in,
                              void* d_out, int out_size) {
    const float* x   = (const float*)d_in[0];
    const float* W1  = (const float*)d_in[1];
    const float* b1  = (const float*)d_in[2];
    const float* gnw = (const float*)d_in[3];
    const float* gnb = (const float*)d_in[4];
    const float* W2  = (const float*)d_in[5];
    const float* b2  = (const float*)d_in[6];
    float* out = (float*)d_out;

    k_zero<<<1, 128>>>();

    dim3 g1(Ww / TLX, Hh / TLY, BATCH);   // 12 x 48 x 8
    k_feat<<<g1, 256>>>(x, W1, b1);

    k_stats<<<1, 64>>>();

    cudaFuncSetAttribute(k_out, cudaFuncAttributeMaxDynamicSharedMemorySize, SMEM3);
    dim3 g3(HW / 128, BATCH);             // 1152 x 8
    k_out<<<g3, 256, SMEM3>>>(gnw, gnb, W2, b2, out);
}

// round 9
// speedup vs baseline: 1.7118x; 1.1026x over previous
#include <cuda_runtime.h>
#include <math.h>
#include <stdint.h>

#define Hh 384
#define Ww 384
#define NC 10
#define HW (384*384)
#define BATCH 8
#define D64 64

typedef unsigned long long u64;

// ---- scratch (static device globals: allocation-free) ----
__device__ float g_h[(size_t)BATCH * D64 * HW];   // 302 MB intermediate h
__device__ float g_stats[128];                    // [b][g][{sum,sumsq}]
__device__ float g_mean[64];
__device__ float g_rstd[64];
__device__ u64   g_w2i[2048];                     // packed W2 pairs [d][pair]

// ---------------- packed f32x2 helpers ----------------
__device__ __forceinline__ u64 pack2(float x, float y) {
    u64 r;
    asm("mov.b64 %0, {%1, %2};" : "=l"(r) : "f"(x), "f"(y));
    return r;
}
__device__ __forceinline__ float2 unpk(u64 v) {
    float2 r;
    asm("mov.b64 {%0, %1}, %2;" : "=f"(r.x), "=f"(r.y) : "l"(v));
    return r;
}
__device__ __forceinline__ u64 fma2(u64 a, u64 b, u64 c) {
    u64 d;
    asm("fma.rn.f32x2 %0, %1, %2, %3;" : "=l"(d) : "l"(a), "l"(b), "l"(c));
    return d;
}
__device__ __forceinline__ u64 add2(u64 a, u64 b) {
    u64 d;
    asm("add.rn.f32x2 %0, %1, %2;" : "=l"(d) : "l"(a), "l"(b));
    return d;
}
__device__ __forceinline__ u64 mul2(u64 a, u64 b) {
    u64 d;
    asm("mul.rn.f32x2 %0, %1, %2;" : "=l"(d) : "l"(a), "l"(b));
    return d;
}
#define NEGM 0x8000000080000000ULL
__device__ __forceinline__ u64 sub2(u64 a, u64 b) { return add2(a, b ^ NEGM); }

// ---------------- K_init: zero stats + pack W2 pairs ----------------
__global__ void k_init(const float* __restrict__ W2) {
    int t = threadIdx.x;
    if (t < 128) g_stats[t] = 0.f;
    for (int i = t; i < 2048; i += 256) {
        int d = i >> 5, p = i & 31;
        g_w2i[d * 32 + p] = pack2(W2[(2 * p) * 64 + d], W2[(2 * p + 1) * 64 + d]);
    }
}

// ---------------- K1: softmax + neighbor features + W1 (f32x2) ----------
#define TLX 64
#define TLY 8
#define EX 68
#define EY 12
#define PAREA (EX * EY)          // 816

__global__ __launch_bounds__(256) void k_feat(const float* __restrict__ x,
                                              const float* __restrict__ W1,
                                              const float* __restrict__ b1) {
    __shared__ float P[NC * PAREA];            // softmax probs, tile + 2px halo
    __shared__ __align__(16) u64 w1p[512];     // {w,w} duplicated
    __shared__ u64 b1p[64];
    __shared__ float sstat[16];

    const int b  = blockIdx.z;
    const int r0 = blockIdx.y * TLY, c0 = blockIdx.x * TLX;
    const int tid = threadIdx.x;

    for (int i = tid; i < 512; i += 256) { float w = W1[i]; w1p[i] = pack2(w, w); }
    if (tid < 64) { float bb = b1[tid]; b1p[tid] = pack2(bb, bb); }
    if (tid < 16) sstat[tid] = 0.f;

    // softmax over C for extended (halo) tile, replicate padding via clamp
    const float* xb = x + (size_t)b * NC * HW;
    for (int i = tid; i < PAREA; i += 256) {
        int er = i / EX, ec2 = i % EX;
        int gr = min(max(r0 + er - 2, 0), Hh - 1);
        int gc = min(max(c0 + ec2 - 2, 0), Ww - 1);
        const float* xp = xb + gr * Ww + gc;
        float v[NC];
        float m = -1e30f;
#pragma unroll
        for (int c = 0; c < NC; c++) { v[c] = xp[(size_t)c * HW]; m = fmaxf(m, v[c]); }
        float ssum = 0.f;
#pragma unroll
        for (int c = 0; c < NC; c++) { v[c] = __expf(v[c] - m); ssum += v[c]; }
        float inv = 1.f / ssum;
#pragma unroll
        for (int c = 0; c < NC; c++) P[c * PAREA + i] = v[c] * inv;
    }
    __syncthreads();

    const int txp = tid & 31;       // pixel-pair index (cols 2*txp, 2*txp+1)
    const int ty  = tid >> 5;       // tile row
    const int rowoff = ty * EX + 2 * txp;   // = halo addr of (row ty, col ec-2)

    // packed accumulators
    u64 macc3 = 0, macc5 = 0, pp = 0;
    u64 vacc3 = 0, vacc5 = 0, pbq3 = 0, pbq5 = 0;
    float maj3x = 0.f, maj3y = 0.f, maj5x = 0.f, maj5y = 0.f;
    float en3x = 0.f, en3y = 0.f, en5x = 0.f, en5y = 0.f;   // Σ pc·log pc

    const u64 K9I  = pack2(1.f / 9.f,  1.f / 9.f);
    const u64 K25I = pack2(1.f / 25.f, 1.f / 25.f);

#pragma unroll 1
    for (int c = 0; c < NC; c++) {
        const float* base = P + c * PAREA + rowoff;
        u64 s5 = 0, q5 = 0, s3 = 0, q3 = 0, pcen = 0;
#pragma unroll
        for (int dr = 0; dr < 5; dr++) {
            const float* rp = base + dr * EX;
            float2 av = *(const float2*)rp;        // v[-2], v[-1]
            float2 bv = *(const float2*)(rp + 2);  // v[0],  v[1]
            float2 cv = *(const float2*)(rp + 4);  // v[2],  v[3]
            u64 p0 = pack2(av.x, av.y);
            u64 p1 = pack2(av.y, bv.x);
            u64 p2 = pack2(bv.x, bv.y);
            u64 p3 = pack2(bv.y, cv.x);
            u64 p4 = pack2(cv.x, cv.y);
            s5 = add2(s5, p0); s5 = add2(s5, p1); s5 = add2(s5, p2);
            s5 = add2(s5, p3); s5 = add2(s5, p4);
            q5 = fma2(p0, p0, q5); q5 = fma2(p1, p1, q5); q5 = fma2(p2, p2, q5);
            q5 = fma2(p3, p3, q5); q5 = fma2(p4, p4, q5);
            if (dr >= 1 && dr <= 3) {
                s3 = add2(s3, p1); s3 = add2(s3, p2); s3 = add2(s3, p3);
                q3 = fma2(p1, p1, q3); q3 = fma2(p2, p2, q3); q3 = fma2(p3, p3, q3);
            }
            if (dr == 2) pcen = p2;
        }
        // match terms: Σ pcen*S and Σ pcen^2
        macc3 = fma2(pcen, s3, macc3);
        macc5 = fma2(pcen, s5, macc5);
        pp    = fma2(pcen, pcen, pp);
        // maj
        float2 s3f = unpk(s3), s5f = unpk(s5);
        maj3x = fmaxf(maj3x, s3f.x); maj3y = fmaxf(maj3y, s3f.y);
        maj5x = fmaxf(maj5x, s5f.x); maj5y = fmaxf(maj5y, s5f.y);
        // var terms: Σ q/K and Σ pb^2
        u64 pb3 = mul2(s3, K9I), pb5 = mul2(s5, K25I);
        vacc3 = fma2(q3, K9I, vacc3);   pbq3 = fma2(pb3, pb3, pbq3);
        vacc5 = fma2(q5, K25I, vacc5);  pbq5 = fma2(pb5, pb5, pbq5);
        // entropy (scalar MUFU)
        float2 pb3f = unpk(pb3), pb5f = unpk(pb5);
        float t0 = fmaxf(pb3f.x, 1e-8f); en3x = fmaf(t0, __logf(t0), en3x);
        float t1 = fmaxf(pb3f.y, 1e-8f); en3y = fmaf(t1, __logf(t1), en3y);
        float t2 = fmaxf(pb5f.x, 1e-8f); en5x = fmaf(t2, __logf(t2), en5x);
        float t3 = fmaxf(pb5f.y, 1e-8f); en5y = fmaf(t3, __logf(t3), en5y);
    }

    const float INV_LOGC = 0.434294481903252f; // 1/ln(10)
    u64 f2[8];
    f2[0] = mul2(sub2(macc3, pp), pack2(1.f / 8.f, 1.f / 8.f));
    f2[1] = mul2(pack2(maj3x, maj3y), K9I);
    f2[2] = pack2(fmaf(en3x, INV_LOGC, 1.f), fmaf(en3y, INV_LOGC, 1.f));
    f2[3] = sub2(vacc3, pbq3);
    f2[4] = mul2(sub2(macc5, pp), pack2(1.f / 24.f, 1.f / 24.f));
    f2[5] = mul2(pack2(maj5x, maj5y), K25I);
    f2[6] = pack2(fmaf(en5x, INV_LOGC, 1.f), fmaf(en5y, INV_LOGC, 1.f));
    f2[7] = sub2(vacc5, pbq5);

    // h = W1 f + b1 (packed over the pixel pair) ; per-group stat partials
    const int pix = (r0 + ty) * Ww + c0 + 2 * txp;
    float* hb = g_h + (size_t)b * D64 * HW + pix;
    u64 gsum2[8], gsq2[8];
#pragma unroll
    for (int g = 0; g < 8; g++) { gsum2[g] = 0; gsq2[g] = 0; }
#pragma unroll 8
    for (int d = 0; d < 64; d++) {
        const u64* wr = &w1p[d * 8];
        u64 acc = b1p[d];
        acc = fma2(wr[0], f2[0], acc);
        acc = fma2(wr[1], f2[1], acc);
        acc = fma2(wr[2], f2[2], acc);
        acc = fma2(wr[3], f2[3], acc);
        acc = fma2(wr[4], f2[4], acc);
        acc = fma2(wr[5], f2[5], acc);
        acc = fma2(wr[6], f2[6], acc);
        acc = fma2(wr[7], f2[7], acc);
        *(float2*)&hb[(size_t)d * HW] = unpk(acc);
        gsum2[d >> 3] = add2(gsum2[d >> 3], acc);
        gsq2[d >> 3]  = fma2(acc, acc, gsq2[d >> 3]);
    }
    // warp reduce -> smem -> global atomics
#pragma unroll
    for (int g = 0; g < 8; g++) {
        float2 sa = unpk(gsum2[g]);
        float2 qa = unpk(gsq2[g]);
        float a = sa.x + sa.y, q = qa.x + qa.y;
#pragma unroll
        for (int o = 16; o; o >>= 1) {
            a += __shfl_xor_sync(0xffffffffu, a, o);
            q += __shfl_xor_sync(0xffffffffu, q, o);
        }
        if (txp == 0) { atomicAdd(&sstat[2 * g], a); atomicAdd(&sstat[2 * g + 1], q); }
    }
    __syncthreads();
    if (tid < 16) atomicAdd(&g_stats[b * 16 + tid], sstat[tid]);
}

// ---------------- K2: finalize GN stats ----------------
__global__ void k_stats() {
    int i = threadIdx.x;
    if (i < 64) {
        const float invN = 1.f / (8.f * (float)HW);
        float s  = g_stats[2 * i];
        float ss = g_stats[2 * i + 1];
        float mean = s * invN;
        float var  = ss * invN - mean * mean;
        g_mean[i] = mean;
        g_rstd[i] = rsqrtf(var + 1e-5f);
    }
}

// -------- K3: GN + GELU + W2 (f32x2, X=128px/Y=4pairs per warp) ----------
// branch-free erf-GELU (A&S 7.1.26, abs err ~1.5e-7)
__device__ __forceinline__ float gelu_fast(float h) {
    float z = h * 0.70710678118f;
    float x = fabsf(z);
    float t = __fdividef(1.f, fmaf(0.3275911f, x, 1.f));
    float p = fmaf(1.061405429f, t, -1.453152027f);
    p = fmaf(p, t, 1.421413741f);
    p = fmaf(p, t, -0.284496736f);
    p = fmaf(p, t, 0.254829592f);
    p = p * t;
    float e = __expf(-x * x);
    float er = fmaf(-p, e, 1.f);
    er = copysignf(er, z);
    return 0.5f * h * (1.f + er);
}

// smem: G [64][128] f32 = 32KB ; w2i [64][32] u64 = 16KB ; sp 768B
#define G_OFF  0
#define W_OFF  32768
#define SP_OFF 49152
#define SMEM3  (49152 + 768)

__global__ void __launch_bounds__(256, 3) k_out(const float* __restrict__ gnw,
                                                const float* __restrict__ gnb,
                                                const float* __restrict__ b2,
                                                float* __restrict__ out) {
    extern __shared__ char s[];
    float* G  = (float*)(s + G_OFF);     // [d][px] 64 x 128
    u64* w2i  = (u64*)(s + W_OFF);       // [d][pair] 64 x 32
    float* sp = (float*)(s + SP_OFF);    // a[64], c[64], b2[64]

    const int b  = blockIdx.y;
    const int p0 = blockIdx.x * 128;
    const int t  = threadIdx.x;

    if (t < 64) {
        int g = t >> 3;
        float a = g_rstd[b * 8 + g] * gnw[t];
        sp[t]       = a;
        sp[64 + t]  = gnb[t] - g_mean[b * 8 + g] * a;
        sp[128 + t] = b2[t];
    }
    // copy prepacked W2 table (coalesced)
    for (int i = t; i < 1024; i += 256)
        *(ulonglong2*)&w2i[i * 2] = *(const ulonglong2*)&g_w2i[i * 2];

    // ---- GN + GELU into G: thread = 4 px x 8 d (h loads issue before sync) ----
    const float* hb = g_h + (size_t)b * D64 * HW + p0;
    const int pxq  = (t & 31) * 4;
    const int dblk = t >> 5;                // 0..7
    float4 hv[8];
#pragma unroll
    for (int j = 0; j < 8; j++)
        hv[j] = *(const float4*)&hb[(size_t)(dblk * 8 + j) * HW + pxq];
    __syncthreads();                        // sp + w2i visible
    {
#pragma unroll
        for (int j = 0; j < 8; j++) {
            int d = dblk * 8 + j;
            float a = sp[d], c = sp[64 + d];
            float4 r;
            r.x = gelu_fast(fmaf(hv[j].x, a, c));
            r.y = gelu_fast(fmaf(hv[j].y, a, c));
            r.z = gelu_fast(fmaf(hv[j].z, a, c));
            r.w = gelu_fast(fmaf(hv[j].w, a, c));
            *(float4*)&G[d * 128 + pxq] = r;
        }
    }
    __syncthreads();

    // ---- GEMM: warp = 128 px x 8 d2 ; thread = 4 px x 4 d2-pairs ----
    const int lane = t & 31;
    const int wrp  = t >> 5;                    // 0..7 -> d2 base 8*wrp
    const int pxb  = lane * 4;
    u64 acc[4][4];                              // [pair][px]
#pragma unroll
    for (int p = 0; p < 4; p++) {
        u64 bp = pack2(sp[128 + 8 * wrp + 2 * p], sp[128 + 8 * wrp + 2 * p + 1]);
#pragma unroll
        for (int x2 = 0; x2 < 4; x2++) acc[p][x2] = bp;
    }

    const float* Gp = G + pxb;
    const u64*   wp = w2i + 4 * wrp;
#pragma unroll 4
    for (int d = 0; d < 64; d++) {
        float4 gv = *(const float4*)Gp;         // 4 px, per-lane LDS.128
        u64 g0 = pack2(gv.x, gv.x);
        u64 g1 = pack2(gv.y, gv.y);
        u64 g2 = pack2(gv.z, gv.z);
        u64 g3 = pack2(gv.w, gv.w);
        ulonglong2 wa = *(const ulonglong2*)(wp);       // pairs 0,1 (uniform)
        ulonglong2 wb = *(const ulonglong2*)(wp + 2);   // pairs 2,3 (uniform)
        acc[0][0] = fma2(wa.x, g0, acc[0][0]);
        acc[0][1] = fma2(wa.x, g1, acc[0][1]);
        acc[0][2] = fma2(wa.x, g2, acc[0][2]);
        acc[0][3] = fma2(wa.x, g3, acc[0][3]);
        acc[1][0] = fma2(wa.y, g0, acc[1][0]);
        acc[1][1] = fma2(wa.y, g1, acc[1][1]);
        acc[1][2] = fma2(wa.y, g2, acc[1][2]);
        acc[1][3] = fma2(wa.y, g3, acc[1][3]);
        acc[2][0] = fma2(wb.x, g0, acc[2][0]);
        acc[2][1] = fma2(wb.x, g1, acc[2][1]);
        acc[2][2] = fma2(wb.x, g2, acc[2][2]);
        acc[2][3] = fma2(wb.x, g3, acc[2][3]);
        acc[3][0] = fma2(wb.y, g0, acc[3][0]);
        acc[3][1] = fma2(wb.y, g1, acc[3][1]);
        acc[3][2] = fma2(wb.y, g2, acc[3][2]);
        acc[3][3] = fma2(wb.y, g3, acc[3][3]);
        Gp += 128; wp += 32;
    }

    // ---- stores: 8 coalesced STG.128 per thread ----
    float* ob = out + (size_t)b * D64 * HW + p0 + pxb;
#pragma unroll
    for (int p = 0; p < 4; p++) {
        int d2 = 8 * wrp + 2 * p;
        float2 a0 = unpk(acc[p][0]);
        float2 a1 = unpk(acc[p][1]);
        float2 a2 = unpk(acc[p][2]);
        float2 a3 = unpk(acc[p][3]);
        float4 lo; lo.x = a0.x; lo.y = a1.x; lo.z = a2.x; lo.w = a3.x;
        float4 hi; hi.x = a0.y; hi.y = a1.y; hi.z = a2.y; hi.w = a3.y;
        *(float4*)&ob[(size_t)d2 * HW]       = lo;
        *(float4*)&ob[(size_t)(d2 + 1) * HW] = hi;
    }
}

// ---------------- launch ----------------
extern "C" void kernel_launch(void* const* d_in, const int* in_sizes, int n_in,
                              void* d_out, int out_size) {
    const float* x   = (const float*)d_in[0];
    const float* W1  = (const float*)d_in[1];
    const float* b1  = (const float*)d_in[2];
    const float* gnw = (const float*)d_in[3];
    const float* gnb = (const float*)d_in[4];
    const float* W2  = (const float*)d_in[5];
    const float* b2  = (const float*)d_in[6];
    float* out = (float*)d_out;

    k_init<<<1, 256>>>(W2);

    dim3 g1(Ww / TLX, Hh / TLY, BATCH);   // 6 x 48 x 8
    k_feat<<<g1, 256>>>(x, W1, b1);

    k_stats<<<1, 64>>>();

    cudaFuncSetAttribute(k_out, cudaFuncAttributeMaxDynamicSharedMemorySize, SMEM3);
    dim3 g3(HW / 128, BATCH);             // 1152 x 8
    k_out<<<g3, 256, SMEM3>>>(gnw, gnb, b2, out);
}